// round 16
// baseline (speedup 1.0000x reference)
#include <cuda_runtime.h>
#include <cuda_fp16.h>
#include <cstdint>

// MOELinearB: out[e] = x[e] @ W[e]^T, E=8, N=4096, R=128, OUT=4096, fp32.
// R16: R13 structure (persistent stealing, smem A/B, bperm-permuted B,
// STG.128 epilogue) + DEFERRED epilogue: double-buffered accumulators let
// tile t-1's stores interleave one-per-ks into tile t's mma loop, so write
// backpressure is absorbed during compute instead of at the barrier.

#define E_   8
#define N_   4096
#define R_   128
#define OUT_ 4096

#define BM 128
#define BN 64
#define NTILE 8
#define THREADS 256
#define NCTA 296
#define NJOBS (E_ * (N_ / BM) * (OUT_ / (BN * NTILE)))   // 2048

#define XTOT (E_ * N_ * R_)
#define WTOT (E_ * OUT_ * R_)

__device__ __half g_xh[XTOT];
__device__ __half g_wh[WTOT];
__device__ int    g_job_ctr;

// Row stride 272 B: (17r + c) mod 8 permutation -> cp.async stores and
// ldmatrix reads bank-conflict-free.
#define RSTRIDE_B 272
#define A_REGION  (128 * RSTRIDE_B)               // 34816
#define B_REGION  (64 * RSTRIDE_B)                // 17408
#define OFF_B     (2 * A_REGION)                  // two A buffers
#define OFF_CTRL  (2 * A_REGION + 2 * B_REGION)   // 104448
#define SMEM_BYTES (OFF_CTRL + 16)                // -> 2 CTAs/SM

// Output-column permutation (R13): B smem slot r holds W row bperm(r).
static __device__ __host__ __forceinline__ int bperm(int r) {
    return (r & 48) | ((r & 6) << 1) | ((r >> 2) & 2) | (r & 1);
}

// ---------------- Kernel 1: fp32 -> fp16 (+ job counter reset) ----------------
__global__ __launch_bounds__(256)
void convert_kernel(const float* __restrict__ X, const float* __restrict__ Wt)
{
    if (blockIdx.x == 0 && threadIdx.x == 0) g_job_ctr = NCTA;

    const int idx = blockIdx.x * blockDim.x + threadIdx.x;
    const int xq = XTOT / 4;
    const float4* src;
    uint2* dst;
    int base;
    if (idx < xq) {
        src = reinterpret_cast<const float4*>(X);
        dst = reinterpret_cast<uint2*>(g_xh);
        base = idx;
    } else {
        src = reinterpret_cast<const float4*>(Wt);
        dst = reinterpret_cast<uint2*>(g_wh);
        base = idx - xq;
    }
    float4 v = src[base];
    __half2 p0 = __floats2half2_rn(v.x, v.y);
    __half2 p1 = __floats2half2_rn(v.z, v.w);
    dst[base] = make_uint2(*reinterpret_cast<uint32_t*>(&p0),
                           *reinterpret_cast<uint32_t*>(&p1));
}

// ---------------- Kernel 2: GEMM ----------------
static __device__ __forceinline__ void mma_f16(float* d, const uint32_t* a,
                                               const uint32_t* b) {
    asm volatile(
        "mma.sync.aligned.m16n8k16.row.col.f32.f16.f16.f32 "
        "{%0,%1,%2,%3}, {%4,%5,%6,%7}, {%8,%9}, {%0,%1,%2,%3};"
        : "+f"(d[0]), "+f"(d[1]), "+f"(d[2]), "+f"(d[3])
        : "r"(a[0]), "r"(a[1]), "r"(a[2]), "r"(a[3]), "r"(b[0]), "r"(b[1]));
}

static __device__ __forceinline__ void ldsm4(uint32_t* r, uint32_t addr) {
    asm volatile("ldmatrix.sync.aligned.m8n8.x4.shared.b16 {%0,%1,%2,%3}, [%4];"
                 : "=r"(r[0]), "=r"(r[1]), "=r"(r[2]), "=r"(r[3]) : "r"(addr));
}

static __device__ __forceinline__ void cp16(uint32_t dst, const void* src) {
    asm volatile("cp.async.cg.shared.global [%0], [%1], 16;"
                 :: "r"(dst), "l"(src) : "memory");
}

static __device__ __forceinline__ uint32_t smem_u32(const void* p) {
    uint32_t a;
    asm("{ .reg .u64 t; cvta.to.shared.u64 t, %1; cvt.u32.u64 %0, t; }"
        : "=r"(a) : "l"(p));
    return a;
}

static __device__ __forceinline__ void decode_job(int j, int& e, int& bm, int& bn0)
{
    e   = j >> 8;
    int rem = j & 255;
    bm  = (rem >> 3) << 7;
    bn0 = (rem & 7) << 9;
}

__global__ __launch_bounds__(THREADS, 2)
void moe_f16_mma_kernel(float* __restrict__ O)
{
    extern __shared__ char smem[];
    const uint32_t sbase = smem_u32(smem);
    volatile int* ctrl = reinterpret_cast<volatile int*>(smem + OFF_CTRL);

    const int tid  = threadIdx.x;
    const int wid  = tid >> 5;
    const int lane = tid & 31;
    const int grp  = lane >> 2;
    const int qc   = lane & 3;
    const int wm   = wid >> 1;   // 0..3 -> M offset wm*32
    const int wn   = wid & 1;    // 0..1 -> N offset wn*32

    const int s_row = tid >> 4;          // B staging: 0..15 (+16/iter)
    const int s_c   = tid & 15;

    const uint32_t a_loff = (uint32_t)((wm * 32 + (lane & 15)) * RSTRIDE_B
                                       + (lane >> 4) * 16);
    const uint32_t b_loff = (uint32_t)((wn * 32 + ((lane >> 4) & 1) * 8 + (lane & 7)) * RSTRIDE_B
                                       + ((lane >> 3) & 1) * 16);

    auto stageA = [&](int ab, const __half* Ap) {
        const uint32_t sb = sbase + (uint32_t)(ab * A_REGION);
#pragma unroll
        for (int it = 0; it < 8; it++) {
            const int idx = tid + it * THREADS;
            const int row = idx >> 4;
            const int c   = idx & 15;
            cp16(sb + (uint32_t)(row * RSTRIDE_B + c * 16), Ap + row * R_ + c * 8);
        }
    };
    auto stageB = [&](int bufi, const __half* Bp) {
        const uint32_t sb = sbase + OFF_B + (uint32_t)(bufi * B_REGION);
#pragma unroll
        for (int it = 0; it < 4; it++) {
            const int row = s_row + it * 16;
            const int grow = bperm(row);
            cp16(sb + (uint32_t)(row * RSTRIDE_B + s_c * 16),
                 Bp + grow * R_ + s_c * 8);
        }
    };

    int job  = blockIdx.x;
    int abuf = 0;

    // prologue: stage A(job) + B tile0 -> one group
    {
        int e, bm, bn0; decode_job(job, e, bm, bn0);
        stageA(0, g_xh + (size_t)e * N_ * R_ + (size_t)bm * R_);
        stageB(0, g_wh + (size_t)e * OUT_ * R_ + (size_t)bn0 * R_);
        asm volatile("cp.async.commit_group;" ::: "memory");
    }

    float acc[2][2][4][4];
    float* prevPtr = O;       // per-thread deferred-store base (tile t-1)
    int havePrev = 0;

    while (job < NJOBS) {
        int e, bm, bn0; decode_job(job, e, bm, bn0);
        const __half* Bg = g_wh + (size_t)e * OUT_ * R_ + (size_t)bn0 * R_;
        float* C = O + (size_t)e * N_ * OUT_;
        const uint32_t sA = sbase + (uint32_t)(abuf * A_REGION);
        int nxt = NJOBS;

#pragma unroll 1
        for (int t = 0; t < NTILE; t++) {
            asm volatile("cp.async.wait_group 0;" ::: "memory");
            __syncthreads();   // B(t) [and A at t==0] visible; old buffer free

            if (t == 7) nxt = ctrl[0];        // popped at head(6), barrier-safe
            if (t < 7) {
                stageB((t + 1) & 1, Bg + (size_t)(t + 1) * BN * R_);
            } else if (nxt < NJOBS) {
                int e2, bm2, bn2; decode_job(nxt, e2, bm2, bn2);
                stageA(abuf ^ 1, g_xh + (size_t)e2 * N_ * R_ + (size_t)bm2 * R_);
                stageB(0, g_wh + (size_t)e2 * OUT_ * R_ + (size_t)bn2 * R_);
            }
            asm volatile("cp.async.commit_group;" ::: "memory");
            if (t == 6 && tid == 0) ctrl[0] = atomicAdd(&g_job_ctr, 1);

            const int cur = t & 1;            // parity continuous across jobs
            const uint32_t bR = sbase + OFF_B + (uint32_t)((t & 1) * B_REGION);

#pragma unroll
            for (int mt = 0; mt < 2; mt++)
#pragma unroll
                for (int nt = 0; nt < 4; nt++)
#pragma unroll
                    for (int q = 0; q < 4; q++)
                        acc[cur][mt][nt][q] = 0.0f;

#pragma unroll
            for (int ks = 0; ks < 8; ks++) {
                const uint32_t kso = (uint32_t)(ks * 32);
                uint32_t af[8], bf[8];
                ldsm4(af + 0, sA + a_loff + 0 * 16 * RSTRIDE_B + kso);
                ldsm4(af + 4, sA + a_loff + 1 * 16 * RSTRIDE_B + kso);
                ldsm4(bf + 0, bR + b_loff + 0 * 16 * RSTRIDE_B + kso);
                ldsm4(bf + 4, bR + b_loff + 1 * 16 * RSTRIDE_B + kso);
#pragma unroll
                for (int mt = 0; mt < 2; mt++)
#pragma unroll
                    for (int nt = 0; nt < 4; nt++)
                        mma_f16(acc[cur][mt][nt], af + mt * 4, bf + nt * 2);

                // deferred store: one STG.128 of tile t-1 per ks step
                if (havePrev) {
                    const int smt = ks >> 2;
                    const int sp  = (ks >> 1) & 1;
                    const int r8  = ks & 1;
                    const int ix  = r8 * 2;
                    const float* a0 = acc[cur ^ 1][smt][2 * sp];
                    const float* a1 = acc[cur ^ 1][smt][2 * sp + 1];
                    float4 v = make_float4(a0[ix], a0[ix + 1], a1[ix], a1[ix + 1]);
                    __stcs(reinterpret_cast<float4*>(
                               prevPtr + (size_t)(smt * 16 + r8 * 8) * OUT_ + sp * 16), v);
                }
            }

            // save deferred-store base for this tile
            prevPtr = C + (size_t)(bm + wm * 32 + grp) * OUT_
                        + (bn0 + t * BN) + wn * 32 + qc * 4;
            havePrev = 1;
        }

        job = nxt;
        abuf ^= 1;
    }

    // flush final tile (parity of t=7 -> acc[1])
#pragma unroll
    for (int s = 0; s < 8; s++) {
        const int smt = s >> 2;
        const int sp  = (s >> 1) & 1;
        const int r8  = s & 1;
        const int ix  = r8 * 2;
        const float* a0 = acc[1][smt][2 * sp];
        const float* a1 = acc[1][smt][2 * sp + 1];
        float4 v = make_float4(a0[ix], a0[ix + 1], a1[ix], a1[ix + 1]);
        __stcs(reinterpret_cast<float4*>(
                   prevPtr + (size_t)(smt * 16 + r8 * 8) * OUT_ + sp * 16), v);
    }
}

extern "C" void kernel_launch(void* const* d_in, const int* in_sizes, int n_in,
                              void* d_out, int out_size)
{
    const float* x = (const float*)d_in[0];   // [E, N, R]
    const float* w = (const float*)d_in[1];   // [E, OUT, R]
    float* out = (float*)d_out;               // [E, N, OUT]

    const int nvec = (XTOT + WTOT) / 4;
    convert_kernel<<<nvec / 256, 256>>>(x, w);

    cudaFuncSetAttribute(moe_f16_mma_kernel,
                         cudaFuncAttributeMaxDynamicSharedMemorySize, SMEM_BYTES);
    moe_f16_mma_kernel<<<NCTA, THREADS, SMEM_BYTES>>>(out);
}

// round 17
// speedup vs baseline: 4.0719x; 4.0719x over previous
#include <cuda_runtime.h>
#include <cuda_fp16.h>
#include <cstdint>

// MOELinearB: out[e] = x[e] @ W[e]^T, E=8, N=4096, R=128, OUT=4096, fp32.
// R17: R16's deferred epilogue redone spill-proof: tile loop unrolled by 2
// with two statically-named accumulator arrays (compile-time parity), so
// tile t-1's 8 STG.128 interleave into tile t's mma loop WITHOUT local-mem
// spills. Otherwise identical to R13 (persistent stealing, bperm-B smem,
// one barrier per tile).

#define E_   8
#define N_   4096
#define R_   128
#define OUT_ 4096

#define BM 128
#define BN 64
#define NTILE 8
#define THREADS 256
#define NCTA 296
#define NJOBS (E_ * (N_ / BM) * (OUT_ / (BN * NTILE)))   // 2048

#define XTOT (E_ * N_ * R_)
#define WTOT (E_ * OUT_ * R_)

__device__ __half g_xh[XTOT];
__device__ __half g_wh[WTOT];
__device__ int    g_job_ctr;

#define RSTRIDE_B 272
#define A_REGION  (128 * RSTRIDE_B)               // 34816
#define B_REGION  (64 * RSTRIDE_B)                // 17408
#define OFF_B     (2 * A_REGION)
#define OFF_CTRL  (2 * A_REGION + 2 * B_REGION)   // 104448
#define SMEM_BYTES (OFF_CTRL + 16)                // -> 2 CTAs/SM

static __device__ __host__ __forceinline__ int bperm(int r) {
    return (r & 48) | ((r & 6) << 1) | ((r >> 2) & 2) | (r & 1);
}

// ---------------- Kernel 1: fp32 -> fp16 (+ job counter reset) ----------------
__global__ __launch_bounds__(256)
void convert_kernel(const float* __restrict__ X, const float* __restrict__ Wt)
{
    if (blockIdx.x == 0 && threadIdx.x == 0) g_job_ctr = NCTA;

    const int idx = blockIdx.x * blockDim.x + threadIdx.x;
    const int xq = XTOT / 4;
    const float4* src;
    uint2* dst;
    int base;
    if (idx < xq) {
        src = reinterpret_cast<const float4*>(X);
        dst = reinterpret_cast<uint2*>(g_xh);
        base = idx;
    } else {
        src = reinterpret_cast<const float4*>(Wt);
        dst = reinterpret_cast<uint2*>(g_wh);
        base = idx - xq;
    }
    float4 v = src[base];
    __half2 p0 = __floats2half2_rn(v.x, v.y);
    __half2 p1 = __floats2half2_rn(v.z, v.w);
    dst[base] = make_uint2(*reinterpret_cast<uint32_t*>(&p0),
                           *reinterpret_cast<uint32_t*>(&p1));
}

// ---------------- Kernel 2: GEMM ----------------
static __device__ __forceinline__ void mma_f16(float* d, const uint32_t* a,
                                               const uint32_t* b) {
    asm volatile(
        "mma.sync.aligned.m16n8k16.row.col.f32.f16.f16.f32 "
        "{%0,%1,%2,%3}, {%4,%5,%6,%7}, {%8,%9}, {%0,%1,%2,%3};"
        : "+f"(d[0]), "+f"(d[1]), "+f"(d[2]), "+f"(d[3])
        : "r"(a[0]), "r"(a[1]), "r"(a[2]), "r"(a[3]), "r"(b[0]), "r"(b[1]));
}

static __device__ __forceinline__ void ldsm4(uint32_t* r, uint32_t addr) {
    asm volatile("ldmatrix.sync.aligned.m8n8.x4.shared.b16 {%0,%1,%2,%3}, [%4];"
                 : "=r"(r[0]), "=r"(r[1]), "=r"(r[2]), "=r"(r[3]) : "r"(addr));
}

static __device__ __forceinline__ void cp16(uint32_t dst, const void* src) {
    asm volatile("cp.async.cg.shared.global [%0], [%1], 16;"
                 :: "r"(dst), "l"(src) : "memory");
}

static __device__ __forceinline__ uint32_t smem_u32(const void* p) {
    uint32_t a;
    asm("{ .reg .u64 t; cvta.to.shared.u64 t, %1; cvt.u32.u64 %0, t; }"
        : "=r"(a) : "l"(p));
    return a;
}

static __device__ __forceinline__ void decode_job(int j, int& e, int& bm, int& bn0)
{
    e   = j >> 8;
    int rem = j & 255;
    bm  = (rem >> 3) << 7;
    bn0 = (rem & 7) << 9;
}

// Tile body: compute tile T into ACCC while draining ACCP (tile T-1).
// All ACC indices are compile-time; ks loop fully unrolled.
#define TILE_BODY(T, ACCC, ACCP)                                               \
    do {                                                                       \
        const uint32_t bR = sbase + OFF_B + (uint32_t)(((T) & 1) * B_REGION);  \
        _Pragma("unroll")                                                      \
        for (int mt = 0; mt < 2; mt++)                                         \
            _Pragma("unroll")                                                  \
            for (int nt = 0; nt < 4; nt++)                                     \
                _Pragma("unroll")                                              \
                for (int q = 0; q < 4; q++)                                    \
                    ACCC[mt][nt][q] = 0.0f;                                    \
        _Pragma("unroll")                                                      \
        for (int ks = 0; ks < 8; ks++) {                                       \
            const uint32_t kso = (uint32_t)(ks * 32);                          \
            uint32_t af[8], bf[8];                                             \
            ldsm4(af + 0, sA + a_loff + 0 * 16 * RSTRIDE_B + kso);             \
            ldsm4(af + 4, sA + a_loff + 1 * 16 * RSTRIDE_B + kso);             \
            ldsm4(bf + 0, bR + b_loff + 0 * 16 * RSTRIDE_B + kso);             \
            ldsm4(bf + 4, bR + b_loff + 1 * 16 * RSTRIDE_B + kso);             \
            _Pragma("unroll")                                                  \
            for (int mt = 0; mt < 2; mt++)                                     \
                _Pragma("unroll")                                              \
                for (int nt = 0; nt < 4; nt++)                                 \
                    mma_f16(ACCC[mt][nt], af + mt * 4, bf + nt * 2);           \
            {   /* deferred STG.128 of tile T-1, one per ks */                 \
                const int smt = ks >> 2;                                       \
                const int sp  = (ks >> 1) & 1;                                 \
                const int r8  = ks & 1;                                        \
                const int ix  = r8 * 2;                                        \
                float4 v = make_float4(ACCP[smt][2 * sp][ix],                  \
                                       ACCP[smt][2 * sp][ix + 1],              \
                                       ACCP[smt][2 * sp + 1][ix],              \
                                       ACCP[smt][2 * sp + 1][ix + 1]);         \
                if (havePrev)                                                  \
                    __stcs(reinterpret_cast<float4*>(                          \
                        prevPtr + (size_t)(smt * 16 + r8 * 8) * OUT_ + sp * 16), v); \
            }                                                                  \
        }                                                                      \
        prevPtr = C + (size_t)(bm + wm * 32 + grp) * OUT_                      \
                    + (bn0 + (T) * BN) + wn * 32 + qc * 4;                     \
        havePrev = 1;                                                          \
    } while (0)

__global__ __launch_bounds__(THREADS, 2)
void moe_f16_mma_kernel(float* __restrict__ O)
{
    extern __shared__ char smem[];
    const uint32_t sbase = smem_u32(smem);
    volatile int* ctrl = reinterpret_cast<volatile int*>(smem + OFF_CTRL);

    const int tid  = threadIdx.x;
    const int wid  = tid >> 5;
    const int lane = tid & 31;
    const int grp  = lane >> 2;
    const int qc   = lane & 3;
    const int wm   = wid >> 1;   // 0..3 -> M offset wm*32
    const int wn   = wid & 1;    // 0..1 -> N offset wn*32

    const int s_row = tid >> 4;
    const int s_c   = tid & 15;

    const uint32_t a_loff = (uint32_t)((wm * 32 + (lane & 15)) * RSTRIDE_B
                                       + (lane >> 4) * 16);
    const uint32_t b_loff = (uint32_t)((wn * 32 + ((lane >> 4) & 1) * 8 + (lane & 7)) * RSTRIDE_B
                                       + ((lane >> 3) & 1) * 16);

    auto stageA = [&](int ab, const __half* Ap) {
        const uint32_t sb = sbase + (uint32_t)(ab * A_REGION);
#pragma unroll
        for (int it = 0; it < 8; it++) {
            const int idx = tid + it * THREADS;
            const int row = idx >> 4;
            const int c   = idx & 15;
            cp16(sb + (uint32_t)(row * RSTRIDE_B + c * 16), Ap + row * R_ + c * 8);
        }
    };
    auto stageB = [&](int bufi, const __half* Bp) {
        const uint32_t sb = sbase + OFF_B + (uint32_t)(bufi * B_REGION);
#pragma unroll
        for (int it = 0; it < 4; it++) {
            const int row = s_row + it * 16;
            const int grow = bperm(row);
            cp16(sb + (uint32_t)(row * RSTRIDE_B + s_c * 16),
                 Bp + grow * R_ + s_c * 8);
        }
    };

    int job  = blockIdx.x;
    int abuf = 0;

    // prologue: stage A(job) + B tile0 -> one group
    {
        int e, bm, bn0; decode_job(job, e, bm, bn0);
        stageA(0, g_xh + (size_t)e * N_ * R_ + (size_t)bm * R_);
        stageB(0, g_wh + (size_t)e * OUT_ * R_ + (size_t)bn0 * R_);
        asm volatile("cp.async.commit_group;" ::: "memory");
    }

    float acc0[2][4][4], acc1[2][4][4];
    float* prevPtr = O;
    int havePrev = 0;

    while (job < NJOBS) {
        int e, bm, bn0; decode_job(job, e, bm, bn0);
        const __half* Bg = g_wh + (size_t)e * OUT_ * R_ + (size_t)bn0 * R_;
        float* C = O + (size_t)e * N_ * OUT_;
        const uint32_t sA = sbase + (uint32_t)(abuf * A_REGION);
        int nxt = NJOBS;

        // tile head: wait/sync, stage next, chain pop (runtime t is fine here)
        auto head = [&](int t) {
            asm volatile("cp.async.wait_group 0;" ::: "memory");
            __syncthreads();
            if (t == 7) nxt = ctrl[0];            // popped at t==6, barrier-safe
            if (t < 7) {
                stageB((t + 1) & 1, Bg + (size_t)(t + 1) * BN * R_);
            } else if (nxt < NJOBS) {
                int e2, bm2, bn2; decode_job(nxt, e2, bm2, bn2);
                stageA(abuf ^ 1, g_xh + (size_t)e2 * N_ * R_ + (size_t)bm2 * R_);
                stageB(0, g_wh + (size_t)e2 * OUT_ * R_ + (size_t)bn2 * R_);
            }
            asm volatile("cp.async.commit_group;" ::: "memory");
            if (t == 6 && tid == 0) ctrl[0] = atomicAdd(&g_job_ctr, 1);
        };

#pragma unroll 1
        for (int tp = 0; tp < NTILE; tp += 2) {
            head(tp);
            TILE_BODY(tp, acc0, acc1);      // even tile -> acc0, drain acc1
            head(tp + 1);
            TILE_BODY(tp + 1, acc1, acc0);  // odd tile -> acc1, drain acc0
        }

        job = nxt;
        abuf ^= 1;
    }

    // flush final tile (t=7 -> acc1)
#pragma unroll
    for (int s = 0; s < 8; s++) {
        const int smt = s >> 2;
        const int sp  = (s >> 1) & 1;
        const int r8  = s & 1;
        const int ix  = r8 * 2;
        float4 v = make_float4(acc1[smt][2 * sp][ix], acc1[smt][2 * sp][ix + 1],
                               acc1[smt][2 * sp + 1][ix], acc1[smt][2 * sp + 1][ix + 1]);
        __stcs(reinterpret_cast<float4*>(
                   prevPtr + (size_t)(smt * 16 + r8 * 8) * OUT_ + sp * 16), v);
    }
}

extern "C" void kernel_launch(void* const* d_in, const int* in_sizes, int n_in,
                              void* d_out, int out_size)
{
    const float* x = (const float*)d_in[0];   // [E, N, R]
    const float* w = (const float*)d_in[1];   // [E, OUT, R]
    float* out = (float*)d_out;               // [E, N, OUT]

    const int nvec = (XTOT + WTOT) / 4;
    convert_kernel<<<nvec / 256, 256>>>(x, w);

    cudaFuncSetAttribute(moe_f16_mma_kernel,
                         cudaFuncAttributeMaxDynamicSharedMemorySize, SMEM_BYTES);
    moe_f16_mma_kernel<<<NCTA, THREADS, SMEM_BYTES>>>(out);
}